// round 14
// baseline (speedup 1.0000x reference)
#include <cuda_runtime.h>
#include <math.h>

// Problem constants
#define B 512
#define S 16
#define H 501
#define C 7
#define KP 512          // padded K (inner dim)
#define DEP_OFF 0
#define ENC_OFF (B*S*S) // 131072

// ---------------- device state ----------------
__device__ float g_gs  [B][KP];        // graph state (padded, tail zeros)
__device__ float g_hin [B][KP];        // h_in buffer (padded, tail zeros)
__device__ float g_zpad[B][KP];        // padded z
__device__ float g_WcatT[KP][1024];    // B matrix for K1: [k][2h+e], e=0 gate, e=1 map
__device__ float g_Whh3T[KP][1536];    // B matrix for K2: [k][3h+j], j=r,z,n
__device__ float g_WlinT[KP][KP];      // W_lin1^T padded
__device__ float g_f0[KP];             // sigmoid(b_gate)*b_map
__device__ float g_ghc[1536];          // (16*f0) @ Whh3T  (constant gh for rb==0 rows)
__device__ int   g_cls[B*S];           // argmax of one-hot node encoding
__device__ float g_d[B][S];            // cached dots nhs[j]·we2
__device__ float g_aprev[B];           // cached dot hv·we1
__device__ int   g_rows16[S][B];       // per-idx compacted rows (rb != 0), stable order
__device__ int   g_cnt16[S];           // per-idx compacted count
__device__ unsigned g_bcount;          // grid barrier arrival count
__device__ unsigned g_bgen;            // grid barrier generation (monotonic)

__device__ __forceinline__ float sigm(float x){ return 1.0f/(1.0f+expf(-x)); }

// ---------------- grid-wide barrier (monotonic generation, replay-safe) ----------------
__device__ __forceinline__ void grid_barrier(){
    __syncthreads();
    if (threadIdx.x == 0){
        __threadfence();
        unsigned snap = *(volatile unsigned*)&g_bgen;
        unsigned old = atomicAdd(&g_bcount, 1u);
        if (old == gridDim.x - 1){
            g_bcount = 0u;
            __threadfence();
            atomicAdd(&g_bgen, 1u);
        } else {
            while (*(volatile unsigned*)&g_bgen == snap) __nanosleep(64);
        }
        __threadfence();
    }
    __syncthreads();
}

// ---------------- init: transpose/interleave weights, pad z, f0, classes ----------------
__global__ void kinit(const float* __restrict__ Wg, const float* __restrict__ Wm,
                      const float* __restrict__ Whh, const float* __restrict__ Wlin,
                      const float* __restrict__ bgate, const float* __restrict__ bmap,
                      const float* __restrict__ z, const float* __restrict__ ne)
{
    int gt = blockIdx.x*blockDim.x + threadIdx.x;
    int gstep = gridDim.x*blockDim.x;
    for (int i=gt; i<KP*1024; i+=gstep){
        int k = i>>10, n = i & 1023; int h = n>>1, e = n&1;
        float v = 0.f;
        if (k<H && h<H) v = e ? Wm[h*H+k] : Wg[h*H+k];
        (&g_WcatT[0][0])[i] = v;
    }
    for (int i=gt; i<KP*1536; i+=gstep){
        int k = i/1536, n = i%1536; int h = n/3, j = n%3;
        float v = 0.f;
        if (k<H && h<H) v = Whh[(j*H+h)*H + k];
        (&g_Whh3T[0][0])[i] = v;
    }
    for (int i=gt; i<KP*KP; i+=gstep){
        int k = i>>9, h = i & 511;
        float v = 0.f;
        if (k<H && h<H) v = Wlin[h*H+k];
        (&g_WlinT[0][0])[i] = v;
    }
    for (int i=gt; i<B*KP; i+=gstep){
        int b = i>>9, k = i & 511;
        (&g_zpad[0][0])[i] = (k<H) ? z[b*H+k] : 0.f;
    }
    for (int i=gt; i<KP; i+=gstep){
        g_f0[i] = (i<H) ? sigm(bgate[i])*bmap[i] : 0.f;
    }
    for (int i=gt; i<B*S; i+=gstep){
        const float* p = ne + i*C;
        int best = 0; float bv = p[0];
        #pragma unroll
        for (int c=1;c<C;c++){ if (p[c] > bv){ bv = p[c]; best = c; } }
        g_cls[i] = best;
    }
}

// ---------------- prep: ghc = (16*f0) @ Whh3T ----------------
__global__ void kprep()
{
    int n = blockIdx.x*blockDim.x + threadIdx.x;   // 0..1535
    if (n >= 1536) return;
    float s = 0.f;
    for (int k = 0; k < KP; k++) s += 16.f*g_f0[k] * g_Whh3T[k][n];
    g_ghc[n] = s;
}

// ---------------- all-idx row compaction (deterministic; dep is a static input) -------
__global__ void kcompact_all(const float* __restrict__ dep)
{
    int idx = blockIdx.x;          // 0..S-1
    int t = threadIdx.x;           // 512 threads, 16 warps
    int w = t >> 5, lane = t & 31;
    if (idx == 0){
        g_rows16[0][t] = t;
        if (t == 0) g_cnt16[0] = B;
        return;
    }
    __shared__ int wsum[16], woff[16];
    __shared__ int total;
    float rb = dep[t*(S*S) + idx*S + (idx-1)];
    int flag = (rb != 0.f) ? 1 : 0;
    unsigned mask = __ballot_sync(0xffffffffu, flag);
    int wprefix = __popc(mask & ((1u << lane) - 1u));
    if (lane == 0) wsum[w] = __popc(mask);
    __syncthreads();
    if (t == 0){
        int run = 0;
        #pragma unroll
        for (int i=0;i<16;i++){ woff[i] = run; run += wsum[i]; }
        total = run;
        g_cnt16[idx] = run;
    }
    __syncthreads();
    if (flag) g_rows16[idx][woff[w] + wprefix] = t;
    for (int i = total + t; i < B; i += 512) g_rows16[idx][i] = 0;
}

// ---------------- gathered 64x64 GEMM core: BM=64, BN=64, BK=16, 256 thr, tile 4x4 ----
__device__ __forceinline__ void gemm_core_g(
    const float* __restrict__ A,      // [..][KP]
    const float* __restrict__ Bm,     // [KP][NB]
    int NB, int n0, const int* srows,
    float acc[4][4], float As[16][68], float Bs[16][64])
{
    int t = threadIdx.x;
    int tx = t & 15, ty = t >> 4;
    int am = t & 63, akq = t >> 6;
    int bk = t >> 4, bn = (t & 15)*4;
    int arow = srows[am];

    for (int k0 = 0; k0 < KP; k0 += 16){
        float4 av = *(const float4*)&A[(size_t)arow*KP + k0 + akq*4];
        float4 bv = *(const float4*)&Bm[(size_t)(k0+bk)*NB + n0 + bn];
        As[akq*4+0][am]=av.x; As[akq*4+1][am]=av.y;
        As[akq*4+2][am]=av.z; As[akq*4+3][am]=av.w;
        *(float4*)&Bs[bk][bn] = bv;
        __syncthreads();
        #pragma unroll
        for (int kk = 0; kk < 16; kk++){
            float4 a4 = *(const float4*)&As[kk][ty*4];
            float4 b4 = *(const float4*)&Bs[kk][tx*4];
            float a[4] = {a4.x,a4.y,a4.z,a4.w};
            float bb[4] = {b4.x,b4.y,b4.z,b4.w};
            #pragma unroll
            for (int i=0;i<4;i++)
                #pragma unroll
                for (int j=0;j<4;j++) acc[i][j] += a[i]*bb[j];
        }
        __syncthreads();
    }
}

// ---------------- GEMM gs0 = zpad @ WlinT + b_lin1 ; writes g_gs and g_hin ----------------
__global__ __launch_bounds__(256) void kgemm0(const float* __restrict__ blin)
{
    __shared__ float As[16][68];
    __shared__ float Bs[16][64];
    __shared__ int srows[64];
    int nt = blockIdx.x & 7, mt = blockIdx.x >> 3;
    int m0 = mt*64, n0 = nt*64;
    int t = threadIdx.x;
    if (t < 64) srows[t] = m0 + t;
    __syncthreads();
    float acc[4][4];
    #pragma unroll
    for (int i=0;i<4;i++)
        #pragma unroll
        for (int j=0;j<4;j++) acc[i][j] = 0.f;
    gemm_core_g(&g_zpad[0][0], &g_WlinT[0][0], KP, n0, srows, acc, As, Bs);
    int tx = t & 15, ty = t >> 4;
    #pragma unroll
    for (int i=0;i<4;i++){
        int m = m0 + ty*4 + i;
        #pragma unroll
        for (int j=0;j<4;j++){
            int h = n0 + tx*4 + j;
            float v = (h<H) ? acc[i][j] + blin[h] : 0.f;
            g_gs[m][h] = v;
            g_hin[m][h] = v;
        }
    }
}

// ---------------- persistent-kernel phase helpers ----------------
__device__ __forceinline__ void gemm1_tile(int u, int idx,
    const float* __restrict__ bgate, const float* __restrict__ bmap,
    float As[16][68], float Bs[16][64], int* srows)
{
    int cnt = g_cnt16[idx];
    int nt = u & 15, mt = u >> 4;
    int m0 = mt*64, n0 = nt*64;
    if (m0 >= cnt) return;
    int t = threadIdx.x;
    __syncthreads();                    // protect srows/As/Bs from previous unit
    if (t < 64) srows[t] = g_rows16[idx][m0 + t];
    __syncthreads();
    float acc[4][4];
    #pragma unroll
    for (int i=0;i<4;i++)
        #pragma unroll
        for (int j=0;j<4;j++) acc[i][j] = 0.f;
    gemm_core_g(&g_gs[0][0], &g_WcatT[0][0], 1024, n0, srows, acc, As, Bs);
    int tx = t & 15, ty = t >> 4;
    int hbase = (n0>>1) + tx*2;
    #pragma unroll
    for (int i=0;i<4;i++){
        int ml = ty*4 + i;
        if (m0 + ml >= cnt) continue;
        int m = srows[ml];
        #pragma unroll
        for (int p=0;p<2;p++){
            int h = hbase + p;
            float val = 0.f;
            if (h < H){
                float f0 = g_f0[h];
                float fv = sigm(acc[i][2*p] + bgate[h]) * (acc[i][2*p+1] + bmap[h]);
                val = 15.f*f0 + fv;
            }
            g_hin[m][h] = val;
        }
    }
}

__device__ __forceinline__ void gemm2_tile(int u, int idx,
    const float* __restrict__ Wih, const float* __restrict__ bih,
    const float* __restrict__ bhh,
    float As[16][68], float Bs[16][64], int* srows)
{
    int cnt = g_cnt16[idx];
    int nt = u & 31, mt = u >> 5;
    int m0 = mt*64, n0 = nt*48;
    if (m0 >= cnt) return;
    int t = threadIdx.x, tx = t & 15, ty = t >> 4;
    int am = t & 63, akq = t >> 6;
    __syncthreads();
    if (t < 64) srows[t] = g_rows16[idx][m0 + t];
    __syncthreads();
    int arow = srows[am];
    float acc[4][3];
    #pragma unroll
    for (int i=0;i<4;i++)
        #pragma unroll
        for (int j=0;j<3;j++) acc[i][j] = 0.f;

    for (int k0 = 0; k0 < KP; k0 += 16){
        float4 av = *(const float4*)&g_hin[arow][k0 + akq*4];
        As[akq*4+0][am]=av.x; As[akq*4+1][am]=av.y;
        As[akq*4+2][am]=av.z; As[akq*4+3][am]=av.w;
        if (t < 192){
            int kb = t/12, nbc = (t%12)*4;
            *(float4*)&Bs[kb][nbc] = *(const float4*)&g_Whh3T[k0+kb][n0 + nbc];
        }
        __syncthreads();
        #pragma unroll
        for (int kk = 0; kk < 16; kk++){
            float4 a4 = *(const float4*)&As[kk][ty*4];
            float b0 = Bs[kk][tx*3+0];
            float b1 = Bs[kk][tx*3+1];
            float b2 = Bs[kk][tx*3+2];
            float a[4] = {a4.x,a4.y,a4.z,a4.w};
            #pragma unroll
            for (int i=0;i<4;i++){
                acc[i][0] += a[i]*b0;
                acc[i][1] += a[i]*b1;
                acc[i][2] += a[i]*b2;
            }
        }
        __syncthreads();
    }

    int h = nt*16 + tx;
    if (h < H){
        float bh_r = bhh[h], bh_z = bhh[H+h], bh_n = bhh[2*H+h];
        float bi_r = bih[h], bi_z = bih[H+h], bi_n = bih[2*H+h];
        #pragma unroll
        for (int i=0;i<4;i++){
            int ml = ty*4 + i;
            if (m0 + ml >= cnt) continue;
            int m = srows[ml];
            int c = g_cls[m*S + idx];
            float gh_r = acc[i][0] + bh_r;
            float gh_z = acc[i][1] + bh_z;
            float gh_n = acc[i][2] + bh_n;
            float gi_r = Wih[(      h)*C + c] + bi_r;
            float gi_z = Wih[(H   + h)*C + c] + bi_z;
            float gi_n = Wih[(2*H + h)*C + c] + bi_n;
            float rr = sigm(gi_r + gh_r);
            float u2 = sigm(gi_z + gh_z);
            float nn = tanhf(gi_n + rr*gh_n);
            float hv = (1.f-u2)*nn + u2*g_hin[m][h];
            g_gs[m][h] = hv;
        }
    }
}

__device__ __forceinline__ void elem_unit(int eu, int idx, const float* __restrict__ dep,
    const float* __restrict__ Wih, const float* __restrict__ bih,
    const float* __restrict__ bhh)
{
    if (idx == 0) return;
    int t = threadIdx.x;
    int r0 = eu * 8;
    for (int rr = 0; rr < 8; rr++){
        int m = r0 + rr;
        float rb = dep[m*(S*S) + idx*S + (idx-1)];
        if (rb != 0.f) continue;
        int c = g_cls[m*S + idx];
        for (int h = t; h < H; h += 256){
            float hin = 16.f * g_f0[h];
            float gh_r = g_ghc[h*3+0] + bhh[h];
            float gh_z = g_ghc[h*3+1] + bhh[H+h];
            float gh_n = g_ghc[h*3+2] + bhh[2*H+h];
            float gi_r = Wih[(      h)*C + c] + bih[h];
            float gi_z = Wih[(H   + h)*C + c] + bih[H+h];
            float gi_n = Wih[(2*H + h)*C + c] + bih[2*H+h];
            float rg = sigm(gi_r + gh_r);
            float u  = sigm(gi_z + gh_z);
            float nn = tanhf(gi_n + rg*gh_n);
            g_gs[m][h] = (1.f-u)*nn + u*hin;
        }
    }
}

__device__ __forceinline__ void light_unit(int b, int idx, bool dovert, bool doedge,
    const float* __restrict__ Wv, const float* __restrict__ bv,
    const float* __restrict__ We, const float* __restrict__ be,
    float* __restrict__ out, float* red)
{
    int t = threadIdx.x, w = t >> 5, lane = t & 31;
    __syncthreads();                    // protect red from previous unit's reader
    if (dovert && w < C){
        float s = 0.f;
        for (int k = lane; k < H; k += 32) s += g_gs[b][k] * Wv[w*H + k];
        #pragma unroll
        for (int o=16;o>0;o>>=1) s += __shfl_down_sync(0xffffffffu, s, o);
        if (lane == 0) red[w] = s + bv[w];
    } else if (doedge && w == 7){
        float s1 = 0.f, s2 = 0.f;
        for (int k = lane; k < H; k += 32){
            float g = g_gs[b][k];
            s1 += g * We[k];
            s2 += g * We[H + k];
        }
        #pragma unroll
        for (int o=16;o>0;o>>=1){
            s1 += __shfl_down_sync(0xffffffffu, s1, o);
            s2 += __shfl_down_sync(0xffffffffu, s2, o);
        }
        if (lane == 0){
            int eidx = idx - 1;
            float bev = be[0];
            float a_old = g_aprev[b];
            float* row = out + DEP_OFF + (b*S + eidx)*S;
            #pragma unroll
            for (int col=0; col<S; col++){
                float v;
                if (col >= eidx) v = 0.f;
                else if (col == eidx-1) v = (a_old + g_d[b][eidx-1] + bev >= 0.f) ? 1.f : 0.f;
                else v = (s1 + g_d[b][col] + bev >= 0.f) ? 1.f : 0.f;
                row[col] = v;
            }
            g_d[b][eidx] = s2;
            g_aprev[b] = s1;
        }
    }
    __syncthreads();
    if (dovert && t == 0){
        float mx = red[0];
        #pragma unroll
        for (int c=1;c<C;c++) mx = fmaxf(mx, red[c]);
        float e[C]; float sum = 0.f;
        #pragma unroll
        for (int c=0;c<C;c++){ e[c] = expf(red[c]-mx); sum += e[c]; }
        float inv = 1.f/sum;
        float* o = out + ENC_OFF + (b*S + idx)*C;
        #pragma unroll
        for (int c=0;c<C;c++) o[c] = e[c]*inv;
    }
}

// ---------------- persistent kernel: all 16 iterations, 2 phases each ----------------
__global__ __launch_bounds__(256, 3) void kpersist(
    const float* __restrict__ dep, const float* __restrict__ bgate,
    const float* __restrict__ bmap, const float* __restrict__ Wv,
    const float* __restrict__ bv, const float* __restrict__ We,
    const float* __restrict__ be, const float* __restrict__ Wih,
    const float* __restrict__ bih, const float* __restrict__ bhh,
    float* __restrict__ out)
{
    __shared__ float As[16][68];
    __shared__ float Bs[16][64];
    __shared__ int srows[64];

    for (int idx = 0; idx < S; ++idx){
        // ---- PHASE A: gemm1 (compacted) + vert(idx) + edge(idx-1), all read g_gs ----
        int gemmUnits = (idx >= 1) ? 128 : 0;
        int nA = gemmUnits + 512;
        for (int u = blockIdx.x; u < nA; u += gridDim.x){
            if (u < gemmUnits)
                gemm1_tile(u, idx, bgate, bmap, As, Bs, srows);
            else
                light_unit(u - gemmUnits, idx, true, idx >= 1, Wv, bv, We, be, out, &As[0][0]);
        }
        grid_barrier();
        // ---- PHASE B: gemm2 (compacted) + constant-GRU rows, write g_gs ----
        for (int u = blockIdx.x; u < 320; u += gridDim.x){
            if (u < 256)
                gemm2_tile(u, idx, Wih, bih, bhh, As, Bs, srows);
            else
                elem_unit(u - 256, idx, dep, Wih, bih, bhh);
        }
        grid_barrier();
    }
    // ---- final edge row (eidx = S-1) ----
    for (int u = blockIdx.x; u < 512; u += gridDim.x)
        light_unit(u, S, false, true, Wv, bv, We, be, out, &As[0][0]);
}

// ---------------- launch ----------------
extern "C" void kernel_launch(void* const* d_in, const int* in_sizes, int n_in,
                              void* d_out, int out_size)
{
    const float* z     = (const float*)d_in[0];
    const float* dep   = (const float*)d_in[1];
    const float* ne    = (const float*)d_in[2];
    const float* Wlin  = (const float*)d_in[3];
    const float* blin  = (const float*)d_in[4];
    const float* Wv    = (const float*)d_in[5];
    const float* bv    = (const float*)d_in[6];
    const float* We    = (const float*)d_in[7];
    const float* be    = (const float*)d_in[8];
    const float* Wg    = (const float*)d_in[9];
    const float* bgate = (const float*)d_in[10];
    const float* Wm    = (const float*)d_in[11];
    const float* bmap  = (const float*)d_in[12];
    const float* Wih   = (const float*)d_in[13];
    const float* bih   = (const float*)d_in[14];
    const float* Whh   = (const float*)d_in[15];
    const float* bhh   = (const float*)d_in[16];
    float* out = (float*)d_out;

    kinit<<<1024, 256>>>(Wg, Wm, Whh, Wlin, bgate, bmap, z, ne);
    kprep<<<6, 256>>>();
    kcompact_all<<<S, 512>>>(dep);
    kgemm0<<<64, 256>>>(blin);

    // co-residency-safe persistent grid
    int sms = 0;
    if (cudaDeviceGetAttribute(&sms, cudaDevAttrMultiProcessorCount, 0) != cudaSuccess || sms <= 0)
        sms = 148;
    int occ = 0;
    if (cudaOccupancyMaxActiveBlocksPerMultiprocessor(&occ, kpersist, 256, 0) != cudaSuccess || occ < 1)
        occ = 1;
    int grid = occ * sms;
    if (grid > 640) grid = 640;

    kpersist<<<grid, 256>>>(dep, bgate, bmap, Wv, bv, We, be, Wih, bih, bhh, out);
    (void)in_sizes; (void)n_in; (void)out_size;
}

// round 15
// speedup vs baseline: 1.3284x; 1.3284x over previous
#include <cuda_runtime.h>
#include <math.h>

// Problem constants
#define B 512
#define S 16
#define H 501
#define C 7
#define KP 512
#define DEP_OFF 0
#define ENC_OFF (B*S*S)
#define GRID_MAX 592

// ---------------- device state ----------------
__device__ float g_gs  [B][KP];
__device__ float g_hin [B][KP];
__device__ float g_zpad[B][KP];
__device__ float g_WcatT[KP][1024];   // [k][2h+e]
__device__ float g_Whh3T[KP][1536];   // [k][3h+j]
__device__ float g_WlinT[KP][KP];
__device__ float g_f0[KP];
__device__ float g_ghc[1536];
__device__ int   g_cls[B*S];
__device__ float g_d[B][S];
__device__ float g_aprev[B];
__device__ int   g_rows16[S][B];
__device__ int   g_cnt16[S];
__device__ unsigned g_bcount;
__device__ unsigned g_bgen;
// split-K partials + fixup counters (monotonic, multiple-of-4 per phase)
__device__ float g_P1[4][B][1024];
__device__ float g_P2[4][B][1536];
__device__ int   g_cP[8][8];
__device__ int   g_cA[8][16];
__device__ int   g_cB[8][32];

__device__ __forceinline__ float sigm(float x){ return 1.0f/(1.0f+expf(-x)); }

// ---------------- grid-wide barrier (monotonic generation, replay-safe) ----------------
__device__ __forceinline__ void grid_barrier(){
    __syncthreads();
    if (threadIdx.x == 0){
        __threadfence();
        unsigned snap = *(volatile unsigned*)&g_bgen;
        unsigned old = atomicAdd(&g_bcount, 1u);
        if (old == gridDim.x - 1){
            g_bcount = 0u;
            __threadfence();
            atomicAdd(&g_bgen, 1u);
        } else {
            while (*(volatile unsigned*)&g_bgen == snap) __nanosleep(64);
        }
        __threadfence();
    }
    __syncthreads();
}

// ---------------- init ----------------
__global__ void kinit(const float* __restrict__ Wg, const float* __restrict__ Wm,
                      const float* __restrict__ Whh, const float* __restrict__ Wlin,
                      const float* __restrict__ bgate, const float* __restrict__ bmap,
                      const float* __restrict__ z, const float* __restrict__ ne)
{
    int gt = blockIdx.x*blockDim.x + threadIdx.x;
    int gstep = gridDim.x*blockDim.x;
    for (int i=gt; i<KP*1024; i+=gstep){
        int k = i>>10, n = i & 1023; int h = n>>1, e = n&1;
        float v = 0.f;
        if (k<H && h<H) v = e ? Wm[h*H+k] : Wg[h*H+k];
        (&g_WcatT[0][0])[i] = v;
    }
    for (int i=gt; i<KP*1536; i+=gstep){
        int k = i/1536, n = i%1536; int h = n/3, j = n%3;
        float v = 0.f;
        if (k<H && h<H) v = Whh[(j*H+h)*H + k];
        (&g_Whh3T[0][0])[i] = v;
    }
    for (int i=gt; i<KP*KP; i+=gstep){
        int k = i>>9, h = i & 511;
        float v = 0.f;
        if (k<H && h<H) v = Wlin[h*H+k];
        (&g_WlinT[0][0])[i] = v;
    }
    for (int i=gt; i<B*KP; i+=gstep){
        int b = i>>9, k = i & 511;
        (&g_zpad[0][0])[i] = (k<H) ? z[b*H+k] : 0.f;
    }
    for (int i=gt; i<KP; i+=gstep){
        g_f0[i] = (i<H) ? sigm(bgate[i])*bmap[i] : 0.f;
    }
    for (int i=gt; i<B*S; i+=gstep){
        const float* p = ne + i*C;
        int best = 0; float bv = p[0];
        #pragma unroll
        for (int c=1;c<C;c++){ if (p[c] > bv){ bv = p[c]; best = c; } }
        g_cls[i] = best;
    }
}

__global__ void kprep()
{
    int n = blockIdx.x*blockDim.x + threadIdx.x;
    if (n >= 1536) return;
    float s = 0.f;
    for (int k = 0; k < KP; k++) s += 16.f*g_f0[k] * g_Whh3T[k][n];
    g_ghc[n] = s;
}

__global__ void kcompact_all(const float* __restrict__ dep)
{
    int idx = blockIdx.x;
    int t = threadIdx.x;
    int w = t >> 5, lane = t & 31;
    if (idx == 0){
        g_rows16[0][t] = t;
        if (t == 0) g_cnt16[0] = B;
        return;
    }
    __shared__ int wsum[16], woff[16];
    __shared__ int total;
    float rb = dep[t*(S*S) + idx*S + (idx-1)];
    int flag = (rb != 0.f) ? 1 : 0;
    unsigned mask = __ballot_sync(0xffffffffu, flag);
    int wprefix = __popc(mask & ((1u << lane) - 1u));
    if (lane == 0) wsum[w] = __popc(mask);
    __syncthreads();
    if (t == 0){
        int run = 0;
        #pragma unroll
        for (int i=0;i<16;i++){ woff[i] = run; run += wsum[i]; }
        total = run;
        g_cnt16[idx] = run;
    }
    __syncthreads();
    if (flag) g_rows16[idx][woff[w] + wprefix] = t;
    for (int i = total + t; i < B; i += 512) g_rows16[idx][i] = 0;
}

// ---------------- split-K GEMM tile core (BM=64,BN=64,BK=16, 8 slices) ----------------
// computes acc over K in [kb, kb+128), A rows from srows
__device__ __forceinline__ void core_64x64_ks(
    const float* __restrict__ A, const float* __restrict__ Bm,
    int NB, int n0, int kb, const int* srows,
    float acc[4][4], float As[16][68], float Bs[16][64])
{
    int t = threadIdx.x;
    int tx = t & 15, ty = t >> 4;
    int am = t & 63, akq = t >> 6;
    int bk = t >> 4, bn = (t & 15)*4;
    int arow = srows[am];
    for (int k0 = kb; k0 < kb + 128; k0 += 16){
        float4 av = *(const float4*)&A[(size_t)arow*KP + k0 + akq*4];
        float4 bv = *(const float4*)&Bm[(size_t)(k0+bk)*NB + n0 + bn];
        As[akq*4+0][am]=av.x; As[akq*4+1][am]=av.y;
        As[akq*4+2][am]=av.z; As[akq*4+3][am]=av.w;
        *(float4*)&Bs[bk][bn] = bv;
        __syncthreads();
        #pragma unroll
        for (int kk = 0; kk < 16; kk++){
            float4 a4 = *(const float4*)&As[kk][ty*4];
            float4 b4 = *(const float4*)&Bs[kk][tx*4];
            float a[4] = {a4.x,a4.y,a4.z,a4.w};
            float bb[4] = {b4.x,b4.y,b4.z,b4.w};
            #pragma unroll
            for (int i=0;i<4;i++)
                #pragma unroll
                for (int j=0;j<4;j++) acc[i][j] += a[i]*bb[j];
        }
        __syncthreads();
    }
}

// signal completion; returns true (to all threads) if this block is the 4th arriver
__device__ __forceinline__ bool signal_last(int* ctr, int* sflag)
{
    __threadfence();
    __syncthreads();
    if (threadIdx.x == 0){
        int old = atomicAdd(ctr, 1);
        *sflag = ((old & 3) == 3) ? 1 : 0;
    }
    __syncthreads();
    return *sflag != 0;
}

// ---------------- P0 unit: gs0 = zpad @ WlinT ----------------
__device__ __forceinline__ void p0_unit(int u, const float* __restrict__ blin,
    float As[16][68], float Bs[16][64], int* srows, int* sflag)
{
    int ks = u & 3, nt = (u>>2) & 7, mb = u >> 5;
    int m0 = mb*64, n0 = nt*64;
    int t = threadIdx.x;
    __syncthreads();
    if (t < 64) srows[t] = m0 + t;
    __syncthreads();
    float acc[4][4];
    #pragma unroll
    for (int i=0;i<4;i++)
        #pragma unroll
        for (int j=0;j<4;j++) acc[i][j] = 0.f;
    core_64x64_ks(&g_zpad[0][0], &g_WlinT[0][0], KP, n0, ks*128, srows, acc, As, Bs);
    int tx = t & 15, ty = t >> 4;
    #pragma unroll
    for (int i=0;i<4;i++)
        *(float4*)&g_P1[ks][m0+ty*4+i][n0+tx*4] = *(float4*)&acc[i][0];
    if (signal_last(&g_cP[mb][nt], sflag)){
        for (int e = t; e < 64*64; e += 256){
            int ml = e >> 6, hh = e & 63;
            int m = m0 + ml, h = n0 + hh;
            float v = __ldcg(&g_P1[0][m][h]) + __ldcg(&g_P1[1][m][h])
                    + __ldcg(&g_P1[2][m][h]) + __ldcg(&g_P1[3][m][h]);
            float r = (h < H) ? v + blin[h] : 0.f;
            g_gs[m][h] = r;
            g_hin[m][h] = r;
        }
    }
}

// ---------------- gemm1 split unit + fused fixup -> g_hin ----------------
__device__ __forceinline__ void g1_unit(int u, int idx, int cnt,
    const float* __restrict__ bgate, const float* __restrict__ bmap,
    float As[16][68], float Bs[16][64], int* srows, int* sflag)
{
    int ks = u & 3, nt = (u>>2) & 15, mb = u >> 6;
    int m0 = mb*64, n0 = nt*64;
    int t = threadIdx.x;
    __syncthreads();
    if (t < 64) srows[t] = g_rows16[idx][m0 + t];
    __syncthreads();
    float acc[4][4];
    #pragma unroll
    for (int i=0;i<4;i++)
        #pragma unroll
        for (int j=0;j<4;j++) acc[i][j] = 0.f;
    core_64x64_ks(&g_gs[0][0], &g_WcatT[0][0], 1024, n0, ks*128, srows, acc, As, Bs);
    int tx = t & 15, ty = t >> 4;
    #pragma unroll
    for (int i=0;i<4;i++)
        *(float4*)&g_P1[ks][m0+ty*4+i][n0+tx*4] = *(float4*)&acc[i][0];
    if (signal_last(&g_cA[mb][nt], sflag)){
        // epilogue for positions [m0,m0+64), h in [nt*32, nt*32+32)
        for (int e = t; e < 64*32; e += 256){
            int pl = e >> 5, hh = e & 31;
            int p = m0 + pl;
            if (p >= cnt) continue;
            int h = nt*32 + hh;
            int m = g_rows16[idx][p];
            int n = 2*h;
            float G = __ldcg(&g_P1[0][p][n])   + __ldcg(&g_P1[1][p][n])
                    + __ldcg(&g_P1[2][p][n])   + __ldcg(&g_P1[3][p][n]);
            float M = __ldcg(&g_P1[0][p][n+1]) + __ldcg(&g_P1[1][p][n+1])
                    + __ldcg(&g_P1[2][p][n+1]) + __ldcg(&g_P1[3][p][n+1]);
            float val = 0.f;
            if (h < H){
                float f0 = g_f0[h];
                val = 15.f*f0 + sigm(G + bgate[h]) * (M + bmap[h]);
            }
            g_hin[m][h] = val;
        }
    }
}

// ---------------- gemm2 split unit + fused GRU fixup -> g_gs ----------------
__device__ __forceinline__ void g2_unit(int u, int idx, int cnt,
    const float* __restrict__ Wih, const float* __restrict__ bih,
    const float* __restrict__ bhh,
    float As[16][68], float Bs[16][64], int* srows, int* sflag)
{
    int ks = u & 3, nt = (u>>2) & 31, mb = u >> 7;
    int m0 = mb*64, n0 = nt*48;
    int t = threadIdx.x, tx = t & 15, ty = t >> 4;
    int am = t & 63, akq = t >> 6;
    __syncthreads();
    if (t < 64) srows[t] = g_rows16[idx][m0 + t];
    __syncthreads();
    int arow = srows[am];
    float acc[4][3];
    #pragma unroll
    for (int i=0;i<4;i++)
        #pragma unroll
        for (int j=0;j<3;j++) acc[i][j] = 0.f;
    int kb = ks*128;
    for (int k0 = kb; k0 < kb + 128; k0 += 16){
        float4 av = *(const float4*)&g_hin[arow][k0 + akq*4];
        As[akq*4+0][am]=av.x; As[akq*4+1][am]=av.y;
        As[akq*4+2][am]=av.z; As[akq*4+3][am]=av.w;
        if (t < 192){
            int kbr = t/12, nbc = (t%12)*4;
            *(float4*)&Bs[kbr][nbc] = *(const float4*)&g_Whh3T[k0+kbr][n0 + nbc];
        }
        __syncthreads();
        #pragma unroll
        for (int kk = 0; kk < 16; kk++){
            float4 a4 = *(const float4*)&As[kk][ty*4];
            float b0 = Bs[kk][tx*3+0];
            float b1 = Bs[kk][tx*3+1];
            float b2 = Bs[kk][tx*3+2];
            float a[4] = {a4.x,a4.y,a4.z,a4.w};
            #pragma unroll
            for (int i=0;i<4;i++){
                acc[i][0] += a[i]*b0;
                acc[i][1] += a[i]*b1;
                acc[i][2] += a[i]*b2;
            }
        }
        __syncthreads();
    }
    #pragma unroll
    for (int i=0;i<4;i++){
        int p = m0 + ty*4 + i;
        g_P2[ks][p][n0+tx*3+0] = acc[i][0];
        g_P2[ks][p][n0+tx*3+1] = acc[i][1];
        g_P2[ks][p][n0+tx*3+2] = acc[i][2];
    }
    if (signal_last(&g_cB[mb][nt], sflag)){
        // GRU epilogue for positions [m0,m0+64), h in [nt*16, nt*16+16)
        for (int e = t; e < 64*16; e += 256){
            int pl = e >> 4, hh = e & 15;
            int p = m0 + pl;
            if (p >= cnt) continue;
            int h = nt*16 + hh;
            if (h >= H) continue;
            int m = g_rows16[idx][p];
            int c = g_cls[m*S + idx];
            int n = 3*h;
            float gh_r = __ldcg(&g_P2[0][p][n+0]) + __ldcg(&g_P2[1][p][n+0])
                       + __ldcg(&g_P2[2][p][n+0]) + __ldcg(&g_P2[3][p][n+0]) + bhh[h];
            float gh_z = __ldcg(&g_P2[0][p][n+1]) + __ldcg(&g_P2[1][p][n+1])
                       + __ldcg(&g_P2[2][p][n+1]) + __ldcg(&g_P2[3][p][n+1]) + bhh[H+h];
            float gh_n = __ldcg(&g_P2[0][p][n+2]) + __ldcg(&g_P2[1][p][n+2])
                       + __ldcg(&g_P2[2][p][n+2]) + __ldcg(&g_P2[3][p][n+2]) + bhh[2*H+h];
            float gi_r = Wih[(      h)*C + c] + bih[h];
            float gi_z = Wih[(H   + h)*C + c] + bih[H+h];
            float gi_n = Wih[(2*H + h)*C + c] + bih[2*H+h];
            float rr = sigm(gi_r + gh_r);
            float u2 = sigm(gi_z + gh_z);
            float nn = tanhf(gi_n + rr*gh_n);
            g_gs[m][h] = (1.f-u2)*nn + u2*g_hin[m][h];
        }
    }
}

// ---------------- constant-GRU rows (rb==0) ----------------
__device__ __forceinline__ void elem_unit(int eu, int idx, const float* __restrict__ dep,
    const float* __restrict__ Wih, const float* __restrict__ bih,
    const float* __restrict__ bhh)
{
    if (idx == 0) return;
    int t = threadIdx.x;
    int r0 = eu * 8;
    for (int rr = 0; rr < 8; rr++){
        int m = r0 + rr;
        float rb = dep[m*(S*S) + idx*S + (idx-1)];
        if (rb != 0.f) continue;
        int c = g_cls[m*S + idx];
        for (int h = t; h < H; h += 256){
            float hin = 16.f * g_f0[h];
            float gh_r = g_ghc[h*3+0] + bhh[h];
            float gh_z = g_ghc[h*3+1] + bhh[H+h];
            float gh_n = g_ghc[h*3+2] + bhh[2*H+h];
            float gi_r = Wih[(      h)*C + c] + bih[h];
            float gi_z = Wih[(H   + h)*C + c] + bih[H+h];
            float gi_n = Wih[(2*H + h)*C + c] + bih[2*H+h];
            float rg = sigm(gi_r + gh_r);
            float u  = sigm(gi_z + gh_z);
            float nn = tanhf(gi_n + rg*gh_n);
            g_gs[m][h] = (1.f-u)*nn + u*hin;
        }
    }
}

// ---------------- vertex softmax + edge row ----------------
__device__ __forceinline__ void light_unit(int b, int idx, bool dovert, bool doedge,
    const float* __restrict__ Wv, const float* __restrict__ bv,
    const float* __restrict__ We, const float* __restrict__ be,
    float* __restrict__ out, float* red)
{
    int t = threadIdx.x, w = t >> 5, lane = t & 31;
    __syncthreads();
    if (dovert && w < C){
        float s = 0.f;
        for (int k = lane; k < H; k += 32) s += g_gs[b][k] * Wv[w*H + k];
        #pragma unroll
        for (int o=16;o>0;o>>=1) s += __shfl_down_sync(0xffffffffu, s, o);
        if (lane == 0) red[w] = s + bv[w];
    } else if (doedge && w == 7){
        float s1 = 0.f, s2 = 0.f;
        for (int k = lane; k < H; k += 32){
            float g = g_gs[b][k];
            s1 += g * We[k];
            s2 += g * We[H + k];
        }
        #pragma unroll
        for (int o=16;o>0;o>>=1){
            s1 += __shfl_down_sync(0xffffffffu, s1, o);
            s2 += __shfl_down_sync(0xffffffffu, s2, o);
        }
        if (lane == 0){
            int eidx = idx - 1;
            float bev = be[0];
            float a_old = g_aprev[b];
            float* row = out + DEP_OFF + (b*S + eidx)*S;
            #pragma unroll
            for (int col=0; col<S; col++){
                float v;
                if (col >= eidx) v = 0.f;
                else if (col == eidx-1) v = (a_old + g_d[b][eidx-1] + bev >= 0.f) ? 1.f : 0.f;
                else v = (s1 + g_d[b][col] + bev >= 0.f) ? 1.f : 0.f;
                row[col] = v;
            }
            g_d[b][eidx] = s2;
            g_aprev[b] = s1;
        }
    }
    __syncthreads();
    if (dovert && t == 0){
        float mx = red[0];
        #pragma unroll
        for (int c=1;c<C;c++) mx = fmaxf(mx, red[c]);
        float e[C]; float sum = 0.f;
        #pragma unroll
        for (int c=0;c<C;c++){ e[c] = expf(red[c]-mx); sum += e[c]; }
        float inv = 1.f/sum;
        float* o = out + ENC_OFF + (b*S + idx)*C;
        #pragma unroll
        for (int c=0;c<C;c++) o[c] = e[c]*inv;
    }
}

// ---------------- persistent kernel ----------------
__global__ __launch_bounds__(256) void kpersist(
    const float* __restrict__ dep, const float* __restrict__ bgate,
    const float* __restrict__ bmap, const float* __restrict__ Wv,
    const float* __restrict__ bv, const float* __restrict__ We,
    const float* __restrict__ be, const float* __restrict__ Wih,
    const float* __restrict__ bih, const float* __restrict__ bhh,
    const float* __restrict__ blin, float* __restrict__ out)
{
    __shared__ float As[16][68];
    __shared__ float Bs[16][64];
    __shared__ int srows[64];
    __shared__ int sflag;
    __shared__ float red[8];

    // P0: gs0 = zpad @ WlinT + blin (split-K, fused fixup)
    for (int u = blockIdx.x; u < 256; u += gridDim.x)
        p0_unit(u, blin, As, Bs, srows, &sflag);
    grid_barrier();

    for (int idx = 0; idx < S; ++idx){
        int cnt = g_cnt16[idx];
        int mt1 = (cnt + 63) >> 6;
        // PHASE A: gemm1 split tiles (+fixup) and light units
        int nG1 = (idx >= 1) ? 64*mt1 : 0;
        int nA = nG1 + 512;
        for (int u = blockIdx.x; u < nA; u += gridDim.x){
            if (u < nG1)
                g1_unit(u, idx, cnt, bgate, bmap, As, Bs, srows, &sflag);
            else
                light_unit(u - nG1, idx, true, idx >= 1, Wv, bv, We, be, out, red);
        }
        grid_barrier();
        // PHASE B: gemm2 split tiles (+GRU fixup) and constant-GRU rows
        int nG2 = 128*mt1;
        int nElem = (idx >= 1) ? 64 : 0;
        int nB = nG2 + nElem;
        for (int u = blockIdx.x; u < nB; u += gridDim.x){
            if (u < nG2)
                g2_unit(u, idx, cnt, Wih, bih, bhh, As, Bs, srows, &sflag);
            else
                elem_unit(u - nG2, idx, dep, Wih, bih, bhh);
        }
        grid_barrier();
    }
    // final edge row (eidx = S-1)
    for (int u = blockIdx.x; u < 512; u += gridDim.x)
        light_unit(u, S, false, true, Wv, bv, We, be, out, red);
}

// ---------------- launch ----------------
extern "C" void kernel_launch(void* const* d_in, const int* in_sizes, int n_in,
                              void* d_out, int out_size)
{
    const float* z     = (const float*)d_in[0];
    const float* dep   = (const float*)d_in[1];
    const float* ne    = (const float*)d_in[2];
    const float* Wlin  = (const float*)d_in[3];
    const float* blin  = (const float*)d_in[4];
    const float* Wv    = (const float*)d_in[5];
    const float* bv    = (const float*)d_in[6];
    const float* We    = (const float*)d_in[7];
    const float* be    = (const float*)d_in[8];
    const float* Wg    = (const float*)d_in[9];
    const float* bgate = (const float*)d_in[10];
    const float* Wm    = (const float*)d_in[11];
    const float* bmap  = (const float*)d_in[12];
    const float* Wih   = (const float*)d_in[13];
    const float* bih   = (const float*)d_in[14];
    const float* Whh   = (const float*)d_in[15];
    const float* bhh   = (const float*)d_in[16];
    float* out = (float*)d_out;

    kinit<<<1024, 256>>>(Wg, Wm, Whh, Wlin, bgate, bmap, z, ne);
    kprep<<<6, 256>>>();
    kcompact_all<<<S, 512>>>(dep);

    int sms = 0;
    if (cudaDeviceGetAttribute(&sms, cudaDevAttrMultiProcessorCount, 0) != cudaSuccess || sms <= 0)
        sms = 148;
    int occ = 0;
    if (cudaOccupancyMaxActiveBlocksPerMultiprocessor(&occ, kpersist, 256, 0) != cudaSuccess || occ < 1)
        occ = 1;
    int grid = occ * sms;
    if (grid > GRID_MAX) grid = GRID_MAX;

    kpersist<<<grid, 256>>>(dep, bgate, bmap, Wv, bv, We, be, Wih, bih, bhh, blin, out);
    (void)in_sizes; (void)n_in; (void)out_size;
}